// round 2
// baseline (speedup 1.0000x reference)
#include <cuda_runtime.h>
#include <cstddef>

#define NN 50000
#define EE 800000
#define MULC 32

#define INV8   0.3535533905932738f   // 1/sqrt(8)
#define INVH   0.3535533905932738f   // 1/sqrt(HID=8)
#define INV3   0.5773502691896258f   // 1/sqrt(3)
#define LIN1   0.1767766952966369f   // 1/sqrt(32)
#define LIN2   0.125f                // 1/sqrt(64)
#define INVSC  0.08838834764831845f  // 1/sqrt(128)

// Scratch (device globals — no runtime allocation allowed). 16B-aligned for
// float4 accesses and red.global.add.v4.f32.
__device__ __align__(16) float g_s1v[(size_t)NN * MULC * 4];  // (n,u,{s1,v1x,v1y,v1z})
__device__ __align__(16) float g_sc [(size_t)NN * 128];       // sc_s[32] | sc_v(u,i)
__device__ __align__(16) float g_acc[(size_t)NN * 256];       // (n,u,{s0,v1xyz,s3,v2xyz})

__device__ __forceinline__ void red4(float* p, float a, float b, float c, float d) {
    asm volatile("red.global.add.v4.f32 [%0], {%1,%2,%3,%4};"
                 :: "l"(__cvta_generic_to_global(p)),
                    "f"(a), "f"(b), "f"(c), "f"(d) : "memory");
}

// ---------------------------------------------------------------------------
// Kernel A: per-node pre-work. One warp handles 2 nodes. Also zeroes g_acc.
// ---------------------------------------------------------------------------
__global__ void __launch_bounds__(256) k_pre(
    const float* __restrict__ nf, const float* __restrict__ nattr,
    const float* __restrict__ W1s, const float* __restrict__ W1v,
    const float* __restrict__ WscS, const float* __restrict__ WscV)
{
    __shared__ float sW1s[1024], sW1v[1024], sWscS[4096], sWscV[4096];
    int tid = threadIdx.x;
    for (int i = tid; i < 1024; i += 256) { sW1s[i] = W1s[i]; sW1v[i] = W1v[i]; }
    for (int i = tid; i < 4096; i += 256) { sWscS[i] = WscS[i]; sWscV[i] = WscV[i]; }
    __syncthreads();

    int warp = blockIdx.x * 8 + (tid >> 5);
    int lane = tid & 31;
    int n0 = warp * 2, n1 = warp * 2 + 1;
    if (n1 >= NN) return;

    // zero accumulator rows for these two nodes
    float4 z4 = make_float4(0.f, 0.f, 0.f, 0.f);
    ((float4*)g_acc)[(size_t)n0 * 64 + lane]      = z4;
    ((float4*)g_acc)[(size_t)n0 * 64 + 32 + lane] = z4;
    ((float4*)g_acc)[(size_t)n1 * 64 + lane]      = z4;
    ((float4*)g_acc)[(size_t)n1 * 64 + 32 + lane] = z4;

    int v = lane;
    const float* f0 = nf + (size_t)n0 * 128;
    const float* f1 = nf + (size_t)n1 * 128;
    float s0r = f0[v], s1r = f1[v];
    float v0x = f0[32 + v*3], v0y = f0[33 + v*3], v0z = f0[34 + v*3];
    float v1x = f1[32 + v*3], v1y = f1[33 + v*3], v1z = f1[34 + v*3];
    float4 a0 = ((const float4*)nattr)[n0];
    float4 a1 = ((const float4*)nattr)[n1];

    float s1a = 0.f, s1b = 0.f;
    float p0x = 0.f, p0y = 0.f, p0z = 0.f, p1x = 0.f, p1y = 0.f, p1z = 0.f;
    float scs0 = 0.f, scs1 = 0.f;
    float q0x = 0.f, q0y = 0.f, q0z = 0.f, q1x = 0.f, q1y = 0.f, q1z = 0.f;

    #pragma unroll
    for (int u = 0; u < 32; u++) {
        float su0 = __shfl_sync(0xffffffffu, s0r, u);
        float su1 = __shfl_sync(0xffffffffu, s1r, u);
        float ux0 = __shfl_sync(0xffffffffu, v0x, u);
        float uy0 = __shfl_sync(0xffffffffu, v0y, u);
        float uz0 = __shfl_sync(0xffffffffu, v0z, u);
        float ux1 = __shfl_sync(0xffffffffu, v1x, u);
        float uy1 = __shfl_sync(0xffffffffu, v1y, u);
        float uz1 = __shfl_sync(0xffffffffu, v1z, u);

        float w1s = sW1s[u*32 + v];
        float w1v = sW1v[u*32 + v];
        float c0 = sWscS[u*128 +      v], c1 = sWscS[u*128 + 32 + v];
        float c2 = sWscS[u*128 + 64 + v], c3 = sWscS[u*128 + 96 + v];
        float d0 = sWscV[u*128 +      v], d1 = sWscV[u*128 + 32 + v];
        float d2 = sWscV[u*128 + 64 + v], d3 = sWscV[u*128 + 96 + v];

        float gs0 = a0.x*c0 + a0.y*c1 + a0.z*c2 + a0.w*c3;
        float gs1 = a1.x*c0 + a1.y*c1 + a1.z*c2 + a1.w*c3;
        float gv0 = a0.x*d0 + a0.y*d1 + a0.z*d2 + a0.w*d3;
        float gv1 = a1.x*d0 + a1.y*d1 + a1.z*d2 + a1.w*d3;

        s1a += su0*w1s;  s1b += su1*w1s;
        p0x += ux0*w1v;  p0y += uy0*w1v;  p0z += uz0*w1v;
        p1x += ux1*w1v;  p1y += uy1*w1v;  p1z += uz1*w1v;
        scs0 += su0*gs0; scs1 += su1*gs1;
        q0x += ux0*gv0;  q0y += uy0*gv0;  q0z += uz0*gv0;
        q1x += ux1*gv1;  q1y += uy1*gv1;  q1z += uz1*gv1;
    }

    ((float4*)g_s1v)[(size_t)n0*32 + v] = make_float4(s1a*LIN1, p0x*LIN1, p0y*LIN1, p0z*LIN1);
    ((float4*)g_s1v)[(size_t)n1*32 + v] = make_float4(s1b*LIN1, p1x*LIN1, p1y*LIN1, p1z*LIN1);

    float* sc0 = g_sc + (size_t)n0 * 128;
    float* sc1 = g_sc + (size_t)n1 * 128;
    sc0[v] = scs0 * INVSC;
    sc0[32 + v*3 + 0] = q0x * INVSC;
    sc0[32 + v*3 + 1] = q0y * INVSC;
    sc0[32 + v*3 + 2] = q0z * INVSC;
    sc1[v] = scs1 * INVSC;
    sc1[32 + v*3 + 0] = q1x * INVSC;
    sc1[32 + v*3 + 1] = q1y * INVSC;
    sc1[32 + v*3 + 2] = q1z * INVSC;
}

// ---------------------------------------------------------------------------
// Kernel B: per-edge work. One warp per edge, lane = channel u.
// edge_index dtype is sniffed at runtime (JAX default config demotes the
// requested int64 to int32; handle both layouts).
// ---------------------------------------------------------------------------
__global__ void __launch_bounds__(256) k_edge(
    const float* __restrict__ ee, const int* __restrict__ eidx32,
    const float* __restrict__ eattr,
    const float* __restrict__ Wfc1, const float* __restrict__ Wfc2)
{
    __shared__ float sF1[64];
    __shared__ float sF2[1024];
    int tid = threadIdx.x;
    for (int i = tid; i < 64;   i += 256) sF1[i] = Wfc1[i];
    for (int i = tid; i < 1024; i += 256) sF2[i] = Wfc2[i];
    __syncthreads();

    int e = blockIdx.x * 8 + (tid >> 5);
    if (e >= EE) return;
    int lane = tid & 31;

    // dtype sniff: for int64 (little-endian, values in [0,2^31)), the high
    // 32-bit words of the first 4 entries are all zero. For random int32
    // indices in [0,50000), P(all four == 0) ~ 1.6e-19. Deterministic per input.
    int ctr, nbr;
    {
        int is64 = 0;
        if (lane == 0)
            is64 = (eidx32[1] == 0) & (eidx32[3] == 0) &
                   (eidx32[5] == 0) & (eidx32[7] == 0);
        is64 = __shfl_sync(0xffffffffu, is64, 0);
        if (is64) {
            const long long* p = (const long long*)eidx32;
            ctr = (int)p[e];
            nbr = (int)p[EE + e];
        } else {
            ctr = eidx32[e];
            nbr = eidx32[EE + e];
        }
    }

    float4 ea = ((const float4*)eattr)[e];                 // es, ev0, ev1, ev2
    float4 eA = ((const float4*)ee)[(size_t)e*2];
    float4 eB = ((const float4*)ee)[(size_t)e*2 + 1];

    // radial MLP hidden: lanes compute h[lane&7] (4x redundant, no divergence)
    int j = lane & 7;
    float x = eA.x*sF1[j]      + eA.y*sF1[8 + j]  + eA.z*sF1[16 + j] + eA.w*sF1[24 + j]
            + eB.x*sF1[32 + j] + eB.y*sF1[40 + j] + eB.z*sF1[48 + j] + eB.w*sF1[56 + j];
    x *= INV8;
    float hj = x / (1.f + __expf(-x));                     // silu

    float w0 = 0.f, w1 = 0.f, w2 = 0.f, w3 = 0.f;
    #pragma unroll
    for (int k = 0; k < 8; k++) {
        float hk = __shfl_sync(0xffffffffu, hj, k);
        w0 += hk * sF2[k*128 +       lane];
        w1 += hk * sF2[k*128 +  32 + lane];
        w2 += hk * sF2[k*128 +  64 + lane];
        w3 += hk * sF2[k*128 +  96 + lane];
    }
    w0 *= INVH; w1 *= INVH; w2 *= INVH; w3 *= INVH;

    float4 xg = ((const float4*)g_s1v)[(size_t)nbr*32 + lane];  // xs, xvx, xvy, xvz
    float dot = xg.y*ea.y + xg.z*ea.z + xg.w*ea.w;
    float s0 = w0 * xg.x * ea.x;
    float s3 = w3 * dot * INV3;
    float av = w1 * xg.x;            // v1 = av * ev
    float bv = w2 * ea.x;            // v2 = bv * xv

    float* base = g_acc + ((size_t)ctr * 32 + lane) * 8;
    red4(base,     s0, av*ea.y, av*ea.z, av*ea.w);
    red4(base + 4, s3, bv*xg.y, bv*xg.z, bv*xg.w);
}

// ---------------------------------------------------------------------------
// Kernel C: per-node post-work. One warp per node, lane = output channel v.
// ---------------------------------------------------------------------------
__global__ void __launch_bounds__(256) k_post(
    const float* __restrict__ W2s, const float* __restrict__ W2v,
    float* __restrict__ out)
{
    __shared__ float sWs[2048], sWv[2048];
    __shared__ float stage[8 * 256];
    int tid = threadIdx.x;
    for (int i = tid; i < 2048; i += 256) { sWs[i] = W2s[i]; sWv[i] = W2v[i]; }
    __syncthreads();

    int n = blockIdx.x * 8 + (tid >> 5);
    if (n >= NN) return;
    int lane = tid & 31;

    float* st = stage + (tid >> 5) * 256;
    float4 A0 = ((const float4*)g_acc)[(size_t)n*64 + lane*2];
    float4 A1 = ((const float4*)g_acc)[(size_t)n*64 + lane*2 + 1];
    ((float4*)st)[lane*2]     = A0;
    ((float4*)st)[lane*2 + 1] = A1;
    __syncwarp();

    float os = 0.f, ox = 0.f, oy = 0.f, oz = 0.f;
    #pragma unroll
    for (int u = 0; u < 32; u++) {
        float4 B0 = ((const float4*)st)[u*2];        // broadcast
        float4 B1 = ((const float4*)st)[u*2 + 1];
        float ws0 = sWs[u*32 + lane], ws1 = sWs[(u + 32)*32 + lane];
        float wv0 = sWv[u*32 + lane], wv1 = sWv[(u + 32)*32 + lane];
        os += B0.x*ws0 + B1.x*ws1;
        ox += B0.y*wv0 + B1.y*wv1;
        oy += B0.z*wv0 + B1.z*wv1;
        oz += B0.w*wv0 + B1.w*wv1;
    }

    const float* sc = g_sc + (size_t)n * 128;
    float* o = out + (size_t)n * 128;
    o[lane]              = os*LIN2 + sc[lane];
    o[32 + lane*3 + 0]   = ox*LIN2 + sc[32 + lane*3 + 0];
    o[32 + lane*3 + 1]   = oy*LIN2 + sc[32 + lane*3 + 1];
    o[32 + lane*3 + 2]   = oz*LIN2 + sc[32 + lane*3 + 2];
}

// ---------------------------------------------------------------------------
extern "C" void kernel_launch(void* const* d_in, const int* in_sizes, int n_in,
                              void* d_out, int out_size)
{
    const float* ee    = (const float*)d_in[0];
    const float* nattr = (const float*)d_in[1];
    const float* nf    = (const float*)d_in[2];
    const int*   eidx  = (const int*)d_in[3];    // int32 or int64 — sniffed in-kernel
    const float* eattr = (const float*)d_in[4];
    const float* W1s   = (const float*)d_in[5];
    const float* W1v   = (const float*)d_in[6];
    const float* Wfc1  = (const float*)d_in[7];
    const float* Wfc2  = (const float*)d_in[8];
    const float* W2s   = (const float*)d_in[9];
    const float* W2v   = (const float*)d_in[10];
    const float* WscS  = (const float*)d_in[11];
    const float* WscV  = (const float*)d_in[12];

    k_pre <<<3125,   256>>>(nf, nattr, W1s, W1v, WscS, WscV);
    k_edge<<<100000, 256>>>(ee, eidx, eattr, Wfc1, Wfc2);
    k_post<<<6250,   256>>>(W2s, W2v, (float*)d_out);
}